// round 16
// baseline (speedup 1.0000x reference)
#include <cuda_runtime.h>
#include <cstdint>

// Problem constants
#define TV      16384   // T * V
#define CTX     16      // T
#define VOCABSZ 1024    // V
#define NB      256     // batch
#define ROWS    8       // W rows per CTA
#define KSLOT   16      // 16 staging slots per thread (= CTX segments)

// out[b, j] = relu( bias[j] + sum_t W[j, x[b,t] + t*V] )
//
// Fused compaction, warp-parallel prep. Columns from different t live in
// disjoint 1024-wide blocks, so dedup is done independently per t: one warp
// per segment (32-word bitmap, 32-lane scan, bit-emit), U laid out as 16
// fixed 256-slot segments (pad = t*1024, dup loads coalesce). Prep is
// ~0.3-0.5us per CTA (vs 2.8us for the serial R14 version), so at grid
// 2048 the overhead is ~1% and hidden by co-resident CTAs' streaming.
// Main row pipeline is byte-identical to the 159.7us R13 structure.

__global__ __launch_bounds__(256, 3)
void lr_fused2_kernel(const int*   __restrict__ x,
                      const float* __restrict__ W,
                      const float* __restrict__ bias,
                      float*       __restrict__ out)
{
    __shared__ uint32_t bm[512];      // 16 segments x 32 words     (2 KB)
    __shared__ int      base_s[512];  // per-word exclusive prefix  (2 KB)
    __shared__ int      s_U[TV / 4];  // 16 x 256 slot column list  (16 KB)
    __shared__ float    s_g[TV / 4];  // staged gathered values     (16 KB)

    const int tid  = threadIdx.x;     // = batch index b
    const int lane = tid & 31;
    const int wrp  = tid >> 5;        // 0..7; warp handles t = wrp, wrp+8
    const int j0   = blockIdx.x * ROWS;

    // ---------- warp-parallel prep (all 8 warps concurrent) ----------
    #pragma unroll
    for (int seg = 0; seg < 2; seg++)
        bm[(wrp + seg * 8) * 32 + lane] = 0;
    __syncwarp();

    #pragma unroll
    for (int seg = 0; seg < 2; seg++) {
        const int t = wrp + seg * 8;
        #pragma unroll
        for (int i = 0; i < 8; i++) {
            int c = x[(lane + 32 * i) * CTX + t];        // 0..1023
            atomicOr(&bm[t * 32 + (c >> 5)], 1u << (c & 31));
        }
    }
    __syncwarp();

    #pragma unroll
    for (int seg = 0; seg < 2; seg++) {
        const int t = wrp + seg * 8;
        uint32_t wv = bm[t * 32 + lane];
        int c = __popc(wv);
        int v = c;
        #pragma unroll
        for (int off = 1; off < 32; off <<= 1) {
            int n = __shfl_up_sync(0xffffffffu, v, off);
            if (lane >= off) v += n;
        }
        const int ebase = v - c;                   // exclusive prefix
        base_s[t * 32 + lane] = ebase;
        const int total = __shfl_sync(0xffffffffu, v, 31);

        // Emit this word's set bits into the segment (sorted ascending).
        int idx = t * 256 + ebase;
        int colbase = t * VOCABSZ + lane * 32;
        while (wv) {
            int b = __ffs(wv) - 1;
            s_U[idx++] = colbase + b;
            wv &= wv - 1;
        }
        // Pad tail slots (dup of t*1024: warp loads coalesce to 1 sector).
        for (int i = total + lane; i < 256; i += 32)
            s_U[t * 256 + i] = t * VOCABSZ;
    }
    __syncthreads();

    // Per-thread ranks: m[t] = slot of col x[b,t] in segment t.
    int m[CTX];
    {
        const int4* xb = (const int4*)(x + tid * CTX);
        #pragma unroll
        for (int q = 0; q < CTX / 4; q++) {
            int4 v = xb[q];
            int cc[4] = {v.x, v.y, v.z, v.w};
            #pragma unroll
            for (int j = 0; j < 4; j++) {
                int t = q * 4 + j;
                int c = cc[j];
                int w = t * 32 + (c >> 5);
                m[t] = t * 256 + base_s[w]
                     + __popc(bm[w] & ((1u << (c & 31)) - 1u));
            }
        }
    }

    // Staging slots owned by this thread (same columns every row).
    int u_idx[KSLOT];
    #pragma unroll
    for (int k = 0; k < KSLOT; k++)
        u_idx[k] = s_U[k * 256 + tid];

    // ---------- main row pipeline (identical to R13 structure) ----------
    // Prefetch row 0 gathers (segment-sorted cols -> ~5 lines/warp; L2-only).
    float pf[KSLOT];
    {
        const float* rowp = W + (size_t)j0 * TV;
        #pragma unroll
        for (int k = 0; k < KSLOT; k++)
            pf[k] = __ldcg(rowp + u_idx[k]);
    }

    float acc[ROWS];

    #pragma unroll 1
    for (int r = 0; r < ROWS; r++) {
        // Publish prefetched row r  (slot k*256+tid == tid+256k).
        #pragma unroll
        for (int k = 0; k < KSLOT; k++)
            s_g[tid + 256 * k] = pf[k];
        __syncthreads();

        // Issue next row's gathers; latency overlaps the smem accumulate.
        if (r + 1 < ROWS) {
            const float* rowp = W + (size_t)(j0 + r + 1) * TV;
            #pragma unroll
            for (int k = 0; k < KSLOT; k++)
                pf[k] = __ldcg(rowp + u_idx[k]);
        }

        // Accumulate this thread's 16 picks.
        float s = 0.f;
        #pragma unroll
        for (int t = 0; t < CTX; t++)
            s += s_g[m[t]];
        acc[r] = s;

        __syncthreads();   // all reads done before s_g is overwritten
    }

    // Epilogue: bias + relu, 2x float4 = 32B contiguous per thread.
    size_t base = (size_t)tid * TV + j0;
    #pragma unroll
    for (int r = 0; r < ROWS; r += 4) {
        float4 bv = *(const float4*)(bias + j0 + r);
        float4 o;
        o.x = fmaxf(acc[r + 0] + bv.x, 0.f);
        o.y = fmaxf(acc[r + 1] + bv.y, 0.f);
        o.z = fmaxf(acc[r + 2] + bv.z, 0.f);
        o.w = fmaxf(acc[r + 3] + bv.w, 0.f);
        *(float4*)(out + base + r) = o;
    }
}

extern "C" void kernel_launch(void* const* d_in, const int* in_sizes, int n_in,
                              void* d_out, int out_size)
{
    // Identify inputs by element count:
    //   x: 256*16 = 4096 (int32), W: 16384*16384 (f32), b: 16384 (f32)
    const int*   x    = nullptr;
    const float* W    = nullptr;
    const float* bias = nullptr;
    for (int i = 0; i < n_in; i++) {
        if (in_sizes[i] == NB * CTX)          x    = (const int*)d_in[i];
        else if (in_sizes[i] == TV)           bias = (const float*)d_in[i];
        else                                  W    = (const float*)d_in[i];
    }
    float* out = (float*)d_out;

    lr_fused2_kernel<<<TV / ROWS, 256>>>(x, W, bias, out);   // 2048 CTAs
}

// round 17
// speedup vs baseline: 1.1120x; 1.1120x over previous
#include <cuda_runtime.h>
#include <cstdint>

// Problem constants
#define TV      16384   // T * V
#define CTX     16      // T
#define VOCABSZ 1024    // V
#define NB      256     // batch
#define ROWS    8       // W rows per CTA (main kernel)
#define KSLOT   16      // staging slots per thread (= CTX segments)

// out[b, j] = relu( bias[j] + sum_t W[j, x[b,t] + t*V] )
//
// Two-kernel compaction with PARALLEL prep + PDL overlap.
//  - prep: 16 blocks (one per timestep segment; segments are disjoint
//    1024-column blocks so dedup is independent). Each block bitmaps its
//    256 x-values, warp-scans, emits its sorted unique column list into a
//    fixed 256-slot segment of d_U (pads = t*1024), and writes per-(b,t)
//    ranks d_m. ~1us total vs ~10us for the old 1-CTA serial prep.
//  - main: byte-identical to the 159.7us R13 streaming loop (DRAM 86.6%):
//    per row, stage the ~3620 needed columns in smem via sorted __ldcg
//    gathers with a register prefetch pipeline; each thread (=batch)
//    accumulates its 16 picks via the rank map. Launched with
//    programmatic stream serialization so its setup overlaps prep's tail;
//    cudaGridDependencySynchronize() gates the first dependent read.

__device__ __align__(16) int d_U[TV / 4];   // 16 x 256 slot column list
__device__ __align__(16) int d_m[NB * CTX]; // slot of col[b,t]

// ---------------------------------------------------------------- prep ----
__global__ void lr_prep16_kernel(const int* __restrict__ x)
{
    __shared__ uint32_t bm[32];      // 1024-bit bitmap for this segment
    __shared__ int      base_s[32];  // exclusive popcount prefix
    __shared__ int      s_tot;

    const int t = blockIdx.x;        // segment = timestep, 16 blocks
    const int b = threadIdx.x;       // batch index, 256 threads

    if (b < 32) bm[b] = 0;
    __syncthreads();

    const int c = x[b * CTX + t];    // 0..1023 (x int32: JAX downcasts i64)
    atomicOr(&bm[c >> 5], 1u << (c & 31));
    __syncthreads();

    if (b < 32) {
        uint32_t wv = bm[b];
        const int pc = __popc(wv);
        int v = pc;
        #pragma unroll
        for (int off = 1; off < 32; off <<= 1) {
            int n = __shfl_up_sync(0xffffffffu, v, off);
            if (b >= off) v += n;
        }
        const int ebase = v - pc;
        base_s[b] = ebase;
        if (b == 31) s_tot = v;

        // Emit this word's set bits (sorted ascending within segment).
        int idx = t * 256 + ebase;
        const int colbase = t * VOCABSZ + b * 32;
        while (wv) {
            int bit = __ffs(wv) - 1;
            d_U[idx++] = colbase + bit;
            wv &= wv - 1;
        }
    }
    __syncthreads();

    // Pad tail slots (dup of t*1024: warp loads broadcast to one sector).
    if (b >= s_tot)   // covers [s_tot, 256) exactly with 256 threads
        d_U[t * 256 + b] = t * VOCABSZ;

    // Rank of this (b, t): global staging slot index.
    const int w = c >> 5;
    d_m[b * CTX + t] = t * 256 + base_s[w]
                     + __popc(bm[w] & ((1u << (c & 31)) - 1u));
}

// ---------------------------------------------------------------- main ----
__global__ __launch_bounds__(256, 3)
void lr_main_kernel(const float* __restrict__ W,
                    const float* __restrict__ bias,
                    float*       __restrict__ out)
{
    __shared__ float s_g[TV / 4];    // staged gathered values (16 KB)

    const int tid = threadIdx.x;     // = batch index b
    const int j0  = blockIdx.x * ROWS;

#if __CUDA_ARCH__ >= 900
    cudaGridDependencySynchronize(); // PDL: wait for prep's writes
#endif

    // Staging slots owned by this thread (same columns every row).
    int u_idx[KSLOT];
    #pragma unroll
    for (int k = 0; k < KSLOT; k++)
        u_idx[k] = d_U[k * 256 + tid];

    // Rank map for this batch.
    int m[CTX];
    {
        const int4* mp = (const int4*)(d_m + tid * CTX);
        #pragma unroll
        for (int q = 0; q < CTX / 4; q++) {
            int4 v = mp[q];
            m[q * 4 + 0] = v.x; m[q * 4 + 1] = v.y;
            m[q * 4 + 2] = v.z; m[q * 4 + 3] = v.w;
        }
    }

    // Prefetch row 0 gathers (sorted cols -> ~5 lines/warp; L2-only).
    float pf[KSLOT];
    {
        const float* rowp = W + (size_t)j0 * TV;
        #pragma unroll
        for (int k = 0; k < KSLOT; k++)
            pf[k] = __ldcg(rowp + u_idx[k]);
    }

    float acc[ROWS];

    #pragma unroll 1
    for (int r = 0; r < ROWS; r++) {
        // Publish prefetched row r (stride-256 stores: conflict-free).
        #pragma unroll
        for (int k = 0; k < KSLOT; k++)
            s_g[k * 256 + tid] = pf[k];
        __syncthreads();

        // Issue next row's gathers; latency overlaps the smem accumulate.
        if (r + 1 < ROWS) {
            const float* rowp = W + (size_t)(j0 + r + 1) * TV;
            #pragma unroll
            for (int k = 0; k < KSLOT; k++)
                pf[k] = __ldcg(rowp + u_idx[k]);
        }

        // Accumulate this thread's 16 picks.
        float s = 0.f;
        #pragma unroll
        for (int t = 0; t < CTX; t++)
            s += s_g[m[t]];
        acc[r] = s;

        __syncthreads();   // all reads done before s_g is overwritten
    }

    // Epilogue: bias + relu, 2x float4 stores (sector-dense).
    size_t base = (size_t)tid * TV + j0;
    #pragma unroll
    for (int r = 0; r < ROWS; r += 4) {
        float4 bv = *(const float4*)(bias + j0 + r);
        float4 o;
        o.x = fmaxf(acc[r + 0] + bv.x, 0.f);
        o.y = fmaxf(acc[r + 1] + bv.y, 0.f);
        o.z = fmaxf(acc[r + 2] + bv.z, 0.f);
        o.w = fmaxf(acc[r + 3] + bv.w, 0.f);
        *(float4*)(out + base + r) = o;
    }
}

extern "C" void kernel_launch(void* const* d_in, const int* in_sizes, int n_in,
                              void* d_out, int out_size)
{
    // Identify inputs by element count:
    //   x: 256*16 = 4096 (int32), W: 16384*16384 (f32), b: 16384 (f32)
    const int*   x    = nullptr;
    const float* W    = nullptr;
    const float* bias = nullptr;
    for (int i = 0; i < n_in; i++) {
        if (in_sizes[i] == NB * CTX)          x    = (const int*)d_in[i];
        else if (in_sizes[i] == TV)           bias = (const float*)d_in[i];
        else                                  W    = (const float*)d_in[i];
    }
    float* out = (float*)d_out;

    lr_prep16_kernel<<<16, 256>>>(x);

    // Main kernel with programmatic dependent launch: its grid launches
    // while prep drains; the griddepsync inside gates dependent reads.
    cudaLaunchAttribute attrs[1];
    attrs[0].id = cudaLaunchAttributeProgrammaticStreamSerialization;
    attrs[0].val.programmaticStreamSerializationAllowed = 1;

    cudaLaunchConfig_t cfg = {};
    cfg.gridDim  = dim3(TV / ROWS);    // 2048 CTAs
    cfg.blockDim = dim3(256);
    cfg.dynamicSmemBytes = 0;
    cfg.stream   = 0;
    cfg.attrs    = attrs;
    cfg.numAttrs = 1;

    cudaError_t err = cudaLaunchKernelEx(&cfg, lr_main_kernel, W, bias, out);
    if (err != cudaSuccess) {
        // Fallback: plain launch (no PDL) if attr unsupported in capture.
        lr_main_kernel<<<TV / ROWS, 256>>>(W, bias, out);
    }
}